// round 2
// baseline (speedup 1.0000x reference)
#include <cuda_runtime.h>
#include <cstdint>

// ---------------------------------------------------------------------------
// MultiHeadSelfAttention: x[B,S,D] @ Wqkv[D,3D] -> q,k,v -> causal attention
// (unscaled logits, mask = -1e9) -> merged[B,S,D] @ Wout[D,D] -> out
// B=2, S=2048, D=1024, H=16, hd=64. All fp32.
// ---------------------------------------------------------------------------

#define BB    2
#define SS    2048
#define DD    1024
#define HH    16
#define HDIM  64
#define QKV_N (3 * DD)

// Scratch (allocation-free rule: __device__ globals)
__device__ float g_qkv[(size_t)BB * SS * 3 * DD];     // [B*S, 3D] row-major
__device__ float g_merged[(size_t)BB * SS * DD];      // [B*S, D]  row-major

// ---------------------------------------------------------------------------
// cp.async helpers (LDGSTS on sm_103a)
// ---------------------------------------------------------------------------
__device__ __forceinline__ void cp_async16(void* smem_dst, const void* gmem_src) {
    uint32_t s = (uint32_t)__cvta_generic_to_shared(smem_dst);
    asm volatile("cp.async.cg.shared.global [%0], [%1], 16;\n" :: "r"(s), "l"(gmem_src));
}
__device__ __forceinline__ void cp_async_commit() {
    asm volatile("cp.async.commit_group;\n" ::);
}
__device__ __forceinline__ void cp_async_wait_all() {
    asm volatile("cp.async.wait_group 0;\n" ::);
}

// ---------------------------------------------------------------------------
// 128x128 tile SGEMM, BK=16, 256 threads, 8x8 microtile, 2-stage cp.async
// double buffering. C[M,N] = A[M,K] @ W[K,N], row-major, dims tile-divisible.
// A staged naturally [m][k] (pad 20 floats -> 16B-aligned rows).
// ---------------------------------------------------------------------------
__global__ __launch_bounds__(256, 2) void sgemm128(const float* __restrict__ A,
                                                   const float* __restrict__ W,
                                                   float* __restrict__ C,
                                                   int M, int N, int K) {
    constexpr int BK = 16;
    __shared__ float As[2][128][20];   // [m][k], row pad 20 (80B, 16B-aligned)
    __shared__ float Ws[2][BK][128];   // [k][n]

    const int t  = threadIdx.x;
    const int tx = t & 15;
    const int ty = t >> 4;

    const float* Ab = A + (size_t)blockIdx.y * 128 * K;
    const float* Wb = W + (size_t)blockIdx.x * 128;
    float*       Cb = C + (size_t)blockIdx.y * 128 * N + (size_t)blockIdx.x * 128;

    float acc[8][8];
#pragma unroll
    for (int i = 0; i < 8; i++)
#pragma unroll
        for (int j = 0; j < 8; j++) acc[i][j] = 0.0f;

    const int KT = K / BK;

    // chunk decompositions (512 16B-chunks each for A and W per stage)
    const int aR0 = t >> 2;            // A chunk: rows t/4 and t/4+64
    const int aC  = (t & 3) << 2;      //          cols {0,4,8,12}
    const int wR0 = t >> 5;            // W chunk: rows t/32 and t/32+8
    const int wC  = (t & 31) << 2;     //          cols {0..124}

#define LOAD_STAGE(kt, buf)                                                     \
    do {                                                                        \
        int _k0 = (kt) * BK;                                                    \
        cp_async16(&As[buf][aR0][aC],      Ab + (size_t)aR0 * K + _k0 + aC);    \
        cp_async16(&As[buf][aR0 + 64][aC], Ab + (size_t)(aR0 + 64) * K + _k0 + aC); \
        cp_async16(&Ws[buf][wR0][wC],      Wb + (size_t)(_k0 + wR0) * N + wC);  \
        cp_async16(&Ws[buf][wR0 + 8][wC],  Wb + (size_t)(_k0 + wR0 + 8) * N + wC); \
    } while (0)

    LOAD_STAGE(0, 0);
    cp_async_commit();

    for (int kt = 0; kt < KT; kt++) {
        const int buf = kt & 1;
        cp_async_wait_all();
        __syncthreads();

        if (kt + 1 < KT) {
            LOAD_STAGE(kt + 1, buf ^ 1);
            cp_async_commit();
        }

#pragma unroll
        for (int kk = 0; kk < BK; kk++) {
            float rA[8], rB[8];
#pragma unroll
            for (int i = 0; i < 8; i++) rA[i] = As[buf][ty * 8 + i][kk];
            *(float4*)&rB[0] = *(const float4*)&Ws[buf][kk][tx * 8];
            *(float4*)&rB[4] = *(const float4*)&Ws[buf][kk][tx * 8 + 4];
#pragma unroll
            for (int i = 0; i < 8; i++)
#pragma unroll
                for (int j = 0; j < 8; j++)
                    acc[i][j] = fmaf(rA[i], rB[j], acc[i][j]);
        }
        __syncthreads();
    }
#undef LOAD_STAGE

#pragma unroll
    for (int i = 0; i < 8; i++) {
        float* cr = Cb + (size_t)(ty * 8 + i) * N + tx * 8;
        *(float4*)cr       = make_float4(acc[i][0], acc[i][1], acc[i][2], acc[i][3]);
        *(float4*)(cr + 4) = make_float4(acc[i][4], acc[i][5], acc[i][6], acc[i][7]);
    }
}

// ---------------------------------------------------------------------------
// Causal flash attention, fp32, unscaled logits, online softmax.
// One block = (b, h, 64-row q-tile). K/V streamed in 32-row tiles up to the
// causal limit. 256 threads: ty=t/16 -> 4 q-rows, tx=t%16 -> 2 k-cols (S) /
// 4 out-cols (O). All shared traffic is LDS.128 (rows padded for alignment).
// ---------------------------------------------------------------------------
__global__ __launch_bounds__(256) void flash_kernel() {
    const int qt = blockIdx.x;   // 0..31
    const int h  = blockIdx.y;   // 0..15
    const int b  = blockIdx.z;   // 0..1

    __shared__ float Qs[64][68];
    __shared__ float Ks[32][68];
    __shared__ float Vs[32][68];
    __shared__ float Ps[64][36];

    const int t  = threadIdx.x;
    const int tx = t & 15;
    const int ty = t >> 4;

    const float* base = g_qkv + (size_t)b * SS * (3 * DD) + h * HDIM;

    // Load Q tile: 64 rows x 64 cols
    {
        int r0 = t >> 4;
        int c  = (t & 15) * 4;
#pragma unroll
        for (int p = 0; p < 4; p++) {
            int r = r0 + p * 16;
            float4 v = *(const float4*)(base + (size_t)(qt * 64 + r) * (3 * DD) + c);
            *(float4*)&Qs[r][c] = v;
        }
    }

    float m_i[4], l_i[4], o[4][4];
#pragma unroll
    for (int i = 0; i < 4; i++) {
        m_i[i] = -1e30f;
        l_i[i] = 0.0f;
#pragma unroll
        for (int j = 0; j < 4; j++) o[i][j] = 0.0f;
    }

    const int nkt = 2 * qt + 2;   // 32-wide k-tiles up to the diagonal
    for (int kt = 0; kt < nkt; kt++) {
        __syncthreads();   // prev O-phase done with Ks/Vs/Ps (and Qs ready, iter 0)

        // Load K and V tiles: 32 rows x 64 cols each
        {
            int r0 = t >> 4;
            int c  = (t & 15) * 4;
#pragma unroll
            for (int p = 0; p < 2; p++) {
                int r = r0 + p * 16;
                const float* kp = base + DD     + (size_t)(kt * 32 + r) * (3 * DD) + c;
                const float* vp = base + 2 * DD + (size_t)(kt * 32 + r) * (3 * DD) + c;
                *(float4*)&Ks[r][c] = *(const float4*)kp;
                *(float4*)&Vs[r][c] = *(const float4*)vp;
            }
        }
        __syncthreads();

        // S = Q @ K^T  (64x32 tile, 4x2 per thread), d unrolled x4, LDS.128
        float s[4][2];
#pragma unroll
        for (int i = 0; i < 4; i++) { s[i][0] = 0.0f; s[i][1] = 0.0f; }
#pragma unroll 4
        for (int d = 0; d < 64; d += 4) {
            float4 k0 = *(const float4*)&Ks[2 * tx + 0][d];
            float4 k1 = *(const float4*)&Ks[2 * tx + 1][d];
#pragma unroll
            for (int i = 0; i < 4; i++) {
                float4 q = *(const float4*)&Qs[4 * ty + i][d];
                s[i][0] = fmaf(q.x, k0.x, fmaf(q.y, k0.y,
                          fmaf(q.z, k0.z, fmaf(q.w, k0.w, s[i][0]))));
                s[i][1] = fmaf(q.x, k1.x, fmaf(q.y, k1.y,
                          fmaf(q.z, k1.z, fmaf(q.w, k1.w, s[i][1]))));
            }
        }

        // Causal mask + online softmax (row spread over 16 tx lanes; xor
        // shuffles with offsets 8..1 reduce within each 16-lane half-warp)
        const int qrow0 = qt * 64 + 4 * ty;
        const int kcol0 = kt * 32 + 2 * tx;
#pragma unroll
        for (int i = 0; i < 4; i++) {
            if (kcol0     > qrow0 + i) s[i][0] = -1e30f;
            if (kcol0 + 1 > qrow0 + i) s[i][1] = -1e30f;

            float rm = fmaxf(s[i][0], s[i][1]);
#pragma unroll
            for (int off = 8; off >= 1; off >>= 1)
                rm = fmaxf(rm, __shfl_xor_sync(0xffffffffu, rm, off));

            float mnew = fmaxf(m_i[i], rm);
            float corr = __expf(m_i[i] - mnew);
            float p0 = __expf(s[i][0] - mnew);
            float p1 = __expf(s[i][1] - mnew);
            float ps = p0 + p1;
#pragma unroll
            for (int off = 8; off >= 1; off >>= 1)
                ps += __shfl_xor_sync(0xffffffffu, ps, off);

            l_i[i] = l_i[i] * corr + ps;
            m_i[i] = mnew;
#pragma unroll
            for (int j = 0; j < 4; j++) o[i][j] *= corr;

            Ps[4 * ty + i][2 * tx + 0] = p0;
            Ps[4 * ty + i][2 * tx + 1] = p1;
        }
        __syncthreads();

        // O += P @ V  (64x64 tile, 4x4 per thread, inner 32), kk unrolled x4
#pragma unroll 2
        for (int kk = 0; kk < 32; kk += 4) {
            float4 v0 = *(const float4*)&Vs[kk + 0][4 * tx];
            float4 v1 = *(const float4*)&Vs[kk + 1][4 * tx];
            float4 v2 = *(const float4*)&Vs[kk + 2][4 * tx];
            float4 v3 = *(const float4*)&Vs[kk + 3][4 * tx];
#pragma unroll
            for (int i = 0; i < 4; i++) {
                float4 p = *(const float4*)&Ps[4 * ty + i][kk];
                o[i][0] = fmaf(p.x, v0.x, fmaf(p.y, v1.x,
                          fmaf(p.z, v2.x, fmaf(p.w, v3.x, o[i][0]))));
                o[i][1] = fmaf(p.x, v0.y, fmaf(p.y, v1.y,
                          fmaf(p.z, v2.y, fmaf(p.w, v3.y, o[i][1]))));
                o[i][2] = fmaf(p.x, v0.z, fmaf(p.y, v1.z,
                          fmaf(p.z, v2.z, fmaf(p.w, v3.z, o[i][2]))));
                o[i][3] = fmaf(p.x, v0.w, fmaf(p.y, v1.w,
                          fmaf(p.z, v2.w, fmaf(p.w, v3.w, o[i][3]))));
            }
        }
    }

    // Normalize and write merged[b, s, h*64 + d]
#pragma unroll
    for (int i = 0; i < 4; i++) {
        int row = qt * 64 + 4 * ty + i;
        float inv = 1.0f / l_i[i];
        float4 v = make_float4(o[i][0] * inv, o[i][1] * inv,
                               o[i][2] * inv, o[i][3] * inv);
        *(float4*)(g_merged + (size_t)(b * SS + row) * DD + h * HDIM + 4 * tx) = v;
    }
}

// ---------------------------------------------------------------------------
extern "C" void kernel_launch(void* const* d_in, const int* in_sizes, int n_in,
                              void* d_out, int out_size) {
    const float* x    = (const float*)d_in[0];   // [B,S,D]
    const float* wqkv = (const float*)d_in[1];   // [D,3D]
    const float* wout = (const float*)d_in[2];   // [D,D]
    float*       out  = (float*)d_out;           // [B,S,D]

    float* qkv;
    float* merged;
    cudaGetSymbolAddress((void**)&qkv, g_qkv);
    cudaGetSymbolAddress((void**)&merged, g_merged);

    // 1) QKV projection: [4096,1024] @ [1024,3072]
    {
        dim3 grid(QKV_N / 128, (BB * SS) / 128);
        sgemm128<<<grid, 256>>>(x, wqkv, qkv, BB * SS, QKV_N, DD);
    }
    // 2) Causal flash attention per (b, h, q-tile)
    {
        dim3 grid(SS / 64, HH, BB);
        flash_kernel<<<grid, 256>>>();
    }
    // 3) Output projection: [4096,1024] @ [1024,1024]
    {
        dim3 grid(DD / 128, (BB * SS) / 128);
        sgemm128<<<grid, 256>>>(merged, wout, out, BB * SS, DD, DD);
    }
}

// round 9
// speedup vs baseline: 1.4344x; 1.4344x over previous
#include <cuda_runtime.h>
#include <cuda_bf16.h>
#include <cstdint>

// ---------------------------------------------------------------------------
// MultiHeadSelfAttention, B=2, S=2048, D=1024, H=16, hd=64 (fp32 in/out).
// GEMMs: bf16 hi/lo split (3 products) on mma.sync.m16n8k16 (HMMA tensor
// cores; tcgen05 PTX is rejected by this harness's compute_103 PTX target).
// Attention: fp32 FFMA flash with exact softmax on unscaled logits.
// Fix vs R5: A-stage loader bound was j<4 (wrote 1024 chunks for a 512-chunk
// tile, corrupting the B buffers); now j<2.
// ---------------------------------------------------------------------------

#define BB    2
#define SS    2048
#define DD    1024
#define HH    16
#define HDIM  64
#define QKVN  3072
#define MTOT  4096          // B*S

// Scratch (__device__ globals only; no allocations allowed)
__device__ float g_qkv[(size_t)MTOT * QKVN];
__device__ float g_merged[(size_t)MTOT * DD];
__device__ __nv_bfloat16 g_xhi[(size_t)MTOT * DD],  g_xlo[(size_t)MTOT * DD];
__device__ __nv_bfloat16 g_mhi[(size_t)MTOT * DD],  g_mlo[(size_t)MTOT * DD];
__device__ __nv_bfloat16 g_w1hi[(size_t)DD * QKVN], g_w1lo[(size_t)DD * QKVN];
__device__ __nv_bfloat16 g_w2hi[(size_t)DD * DD],   g_w2lo[(size_t)DD * DD];

// ---------------------------------------------------------------------------
// PTX helpers (all non-arch-specific: sm_80-era, valid in compute_103 PTX)
// ---------------------------------------------------------------------------
__device__ __forceinline__ uint32_t smem_u32(const void* p) {
    uint32_t a;
    asm("{ .reg .u64 t; cvta.to.shared.u64 t, %1; cvt.u32.u64 %0, t; }" : "=r"(a) : "l"(p));
    return a;
}
__device__ __forceinline__ void cp_async16(uint32_t smem_dst, const void* gmem_src) {
    asm volatile("cp.async.cg.shared.global [%0], [%1], 16;" :: "r"(smem_dst), "l"(gmem_src));
}
__device__ __forceinline__ void cp_commit()   { asm volatile("cp.async.commit_group;"); }
__device__ __forceinline__ void cp_wait_all() { asm volatile("cp.async.wait_group 0;" ::: "memory"); }

__device__ __forceinline__ void ldsm_x4(uint32_t* r, uint32_t addr) {
    asm volatile("ldmatrix.sync.aligned.m8n8.x4.shared.b16 {%0,%1,%2,%3}, [%4];"
                 : "=r"(r[0]), "=r"(r[1]), "=r"(r[2]), "=r"(r[3]) : "r"(addr));
}
__device__ __forceinline__ void ldsm_x4_t(uint32_t* r, uint32_t addr) {
    asm volatile("ldmatrix.sync.aligned.m8n8.x4.trans.shared.b16 {%0,%1,%2,%3}, [%4];"
                 : "=r"(r[0]), "=r"(r[1]), "=r"(r[2]), "=r"(r[3]) : "r"(addr));
}
__device__ __forceinline__ void mma_bf16(float* c, const uint32_t* a, const uint32_t* b) {
    asm volatile("mma.sync.aligned.m16n8k16.row.col.f32.bf16.bf16.f32 "
                 "{%0,%1,%2,%3}, {%4,%5,%6,%7}, {%8,%9}, {%0,%1,%2,%3};"
                 : "+f"(c[0]), "+f"(c[1]), "+f"(c[2]), "+f"(c[3])
                 : "r"(a[0]), "r"(a[1]), "r"(a[2]), "r"(a[3]), "r"(b[0]), "r"(b[1]));
}

// ---------------------------------------------------------------------------
// Split converts: v = hi + lo (two bf16, ~16 mantissa bits combined)
// ---------------------------------------------------------------------------
__device__ __forceinline__ void split1(float v, __nv_bfloat16& h, __nv_bfloat16& l) {
    h = __float2bfloat16(v);
    l = __float2bfloat16(v - __bfloat162float(h));
}

__global__ void convert_split(const float* __restrict__ src,
                              __nv_bfloat16* __restrict__ hi,
                              __nv_bfloat16* __restrict__ lo, int n4) {
    int i = blockIdx.x * blockDim.x + threadIdx.x;
    if (i >= n4) return;
    float4 v = ((const float4*)src)[i];
    __nv_bfloat16 h0, h1, h2, h3, l0, l1, l2, l3;
    split1(v.x, h0, l0); split1(v.y, h1, l1);
    split1(v.z, h2, l2); split1(v.w, h3, l3);
    __nv_bfloat162 a, b, c, d;
    a.x = h0; a.y = h1;  b.x = h2; b.y = h3;
    c.x = l0; c.y = l1;  d.x = l2; d.y = l3;
    ((__nv_bfloat162*)hi)[2 * i]     = a;
    ((__nv_bfloat162*)hi)[2 * i + 1] = b;
    ((__nv_bfloat162*)lo)[2 * i]     = c;
    ((__nv_bfloat162*)lo)[2 * i + 1] = d;
}

// ---------------------------------------------------------------------------
// bf16x3 split GEMM on mma.sync.  C[M,N] = A[M,K] @ B[K,N]  (both row-major).
// CTA tile 128x128, BK=32, 256 threads = 8 warps in a 4(m) x 2(n) grid,
// warp tile 32x64.  cp.async double-buffered.
// Smem pitches: A rows 40 bf16 (80B), B rows 136 bf16 (272B) -- both walk
// all eight 16B banks across 8 consecutive rows => conflict-free ldmatrix.
// ---------------------------------------------------------------------------
#define A_PITCH 40          // bf16 units
#define B_PITCH 136
#define A_BYTES (128 * A_PITCH * 2)     // 10240
#define B_BYTES (32 * B_PITCH * 2)      // 8704
#define STG_BYTES (2 * A_BYTES + 2 * B_BYTES)   // Ahi,Alo,Bhi,Blo = 37888
#define OFF_AHI 0
#define OFF_ALO A_BYTES
#define OFF_BHI (2 * A_BYTES)
#define OFF_BLO (2 * A_BYTES + B_BYTES)
#define GEMM_SMEM (2 * STG_BYTES)       // 75776

__global__ __launch_bounds__(256, 1)
void gemm_mma(const __nv_bfloat16* __restrict__ Ahi, const __nv_bfloat16* __restrict__ Alo,
              const __nv_bfloat16* __restrict__ Bhi, const __nv_bfloat16* __restrict__ Blo,
              float* __restrict__ C, int M, int N, int K) {
    extern __shared__ char smem[];
    const uint32_t sb = smem_u32(smem);

    const int t    = threadIdx.x;
    const int lane = t & 31;
    const int w    = t >> 5;
    const int wm   = w & 3;         // 4 warps along m
    const int wn   = w >> 2;        // 2 warps along n
    const int m0   = blockIdx.y * 128;
    const int n0   = blockIdx.x * 128;

    const int lr = lane & 15;       // ldmatrix row within 16x16 block
    const int lc = lane >> 4;       // 0/1 -> 8-col half

    float acc[2][8][4];
#pragma unroll
    for (int i = 0; i < 2; i++)
#pragma unroll
        for (int j = 0; j < 8; j++)
#pragma unroll
            for (int k = 0; k < 4; k++) acc[i][j][k] = 0.0f;

    const int KT = K >> 5;   // BK = 32

    // ---- stage loader: A = 128x32 (512 chunks), B = 32x128 (512 chunks)
#define LOAD_STAGE(s, buf)                                                       \
    do {                                                                         \
        const int _k0 = (s) << 5;                                                \
        const uint32_t _sB = sb + (uint32_t)(buf) * STG_BYTES;                   \
        _Pragma("unroll")                                                        \
        for (int j = 0; j < 2; j++) {        /* A: 512 chunks / component */     \
            int id = j * 256 + t;                                                \
            int r = id >> 2, kc = (id & 3) << 3;                                 \
            uint32_t o = (uint32_t)(r * (A_PITCH * 2) + kc * 2);                 \
            size_t g = (size_t)(m0 + r) * K + _k0 + kc;                          \
            cp_async16(_sB + OFF_AHI + o, Ahi + g);                              \
            cp_async16(_sB + OFF_ALO + o, Alo + g);                              \
        }                                                                        \
        _Pragma("unroll")                                                        \
        for (int j = 0; j < 2; j++) {        /* B: 512 chunks / component */     \
            int id = j * 256 + t;                                                \
            int r = id >> 4, nc = (id & 15) << 3;                                \
            uint32_t o = (uint32_t)(r * (B_PITCH * 2) + nc * 2);                 \
            size_t g = (size_t)(_k0 + r) * N + n0 + nc;                          \
            cp_async16(_sB + OFF_BHI + o, Bhi + g);                              \
            cp_async16(_sB + OFF_BLO + o, Blo + g);                              \
        }                                                                        \
    } while (0)

    LOAD_STAGE(0, 0);
    cp_commit();

    for (int s = 0; s < KT; s++) {
        const int buf = s & 1;
        cp_wait_all();
        __syncthreads();

        if (s + 1 < KT) {
            LOAD_STAGE(s + 1, buf ^ 1);
            cp_commit();
        }

        const uint32_t stg = sb + (uint32_t)buf * STG_BYTES;
#pragma unroll
        for (int ks = 0; ks < 2; ks++) {            // two k16 steps per stage
            const int k16 = ks << 4;
            uint32_t ahi[2][4], alo[2][4], bhi[4][4], blo[4][4];
#pragma unroll
            for (int mi = 0; mi < 2; mi++) {
                uint32_t ao = (uint32_t)((wm * 32 + mi * 16 + lr) * (A_PITCH * 2)
                                         + (k16 + lc * 8) * 2);
                ldsm_x4(ahi[mi], stg + OFF_AHI + ao);
                ldsm_x4(alo[mi], stg + OFF_ALO + ao);
            }
#pragma unroll
            for (int g = 0; g < 4; g++) {
                uint32_t bo = (uint32_t)((k16 + lr) * (B_PITCH * 2)
                                         + (wn * 64 + g * 16 + lc * 8) * 2);
                ldsm_x4_t(bhi[g], stg + OFF_BHI + bo);
                ldsm_x4_t(blo[g], stg + OFF_BLO + bo);
            }
#pragma unroll
            for (int mi = 0; mi < 2; mi++)
#pragma unroll
                for (int g = 0; g < 4; g++) {
                    // two n8 tiles per 16-col ldmatrix group
                    mma_bf16(acc[mi][g * 2 + 0], ahi[mi], &bhi[g][0]);
                    mma_bf16(acc[mi][g * 2 + 0], ahi[mi], &blo[g][0]);
                    mma_bf16(acc[mi][g * 2 + 0], alo[mi], &bhi[g][0]);
                    mma_bf16(acc[mi][g * 2 + 1], ahi[mi], &bhi[g][2]);
                    mma_bf16(acc[mi][g * 2 + 1], ahi[mi], &blo[g][2]);
                    mma_bf16(acc[mi][g * 2 + 1], alo[mi], &bhi[g][2]);
                }
        }
        __syncthreads();
    }
#undef LOAD_STAGE

    // ---- epilogue: m16n8 accumulator layout -> float2 stores
    const int gq = lane >> 2;            // row within 8-row group
    const int tq = lane & 3;             // column pair index
#pragma unroll
    for (int mi = 0; mi < 2; mi++)
#pragma unroll
        for (int nj = 0; nj < 8; nj++) {
            int row = m0 + wm * 32 + mi * 16 + gq;
            int col = n0 + wn * 64 + nj * 8 + tq * 2;
            float2 v0 = make_float2(acc[mi][nj][0], acc[mi][nj][1]);
            float2 v1 = make_float2(acc[mi][nj][2], acc[mi][nj][3]);
            *(float2*)(C + (size_t)row * N + col)       = v0;
            *(float2*)(C + (size_t)(row + 8) * N + col) = v1;
        }
}

// ---------------------------------------------------------------------------
// Causal flash attention, fp32, unscaled logits, online softmax.
// qt reversed across blockIdx.x so heavy diagonal tiles start in wave 1.
// ---------------------------------------------------------------------------
__global__ __launch_bounds__(256) void flash_kernel() {
    const int qt = (int)gridDim.x - 1 - (int)blockIdx.x;
    const int h  = blockIdx.y;
    const int b  = blockIdx.z;

    __shared__ float Qs[64][68];
    __shared__ float Ks[32][68];
    __shared__ float Vs[32][68];
    __shared__ float Ps[64][36];

    const int t = threadIdx.x, tx = t & 15, ty = t >> 4;
    const float* base = g_qkv + (size_t)b * SS * QKVN + h * HDIM;

    {
        int r0 = t >> 4, c = (t & 15) * 4;
#pragma unroll
        for (int p = 0; p < 4; p++) {
            int r = r0 + p * 16;
            *(float4*)&Qs[r][c] = *(const float4*)(base + (size_t)(qt * 64 + r) * QKVN + c);
        }
    }

    float m_i[4], l_i[4], o[4][4];
#pragma unroll
    for (int i = 0; i < 4; i++) {
        m_i[i] = -1e30f; l_i[i] = 0.0f;
#pragma unroll
        for (int j = 0; j < 4; j++) o[i][j] = 0.0f;
    }

    const int nkt = 2 * qt + 2;
    for (int kt = 0; kt < nkt; kt++) {
        __syncthreads();
        {
            int r0 = t >> 4, c = (t & 15) * 4;
#pragma unroll
            for (int p = 0; p < 2; p++) {
                int r = r0 + p * 16;
                const float* kp = base + DD     + (size_t)(kt * 32 + r) * QKVN + c;
                const float* vp = base + 2 * DD + (size_t)(kt * 32 + r) * QKVN + c;
                *(float4*)&Ks[r][c] = *(const float4*)kp;
                *(float4*)&Vs[r][c] = *(const float4*)vp;
            }
        }
        __syncthreads();

        float s[4][2];
#pragma unroll
        for (int i = 0; i < 4; i++) { s[i][0] = 0.0f; s[i][1] = 0.0f; }
#pragma unroll 4
        for (int d = 0; d < 64; d += 4) {
            float4 k0 = *(const float4*)&Ks[2 * tx + 0][d];
            float4 k1 = *(const float4*)&Ks[2 * tx + 1][d];
#pragma unroll
            for (int i = 0; i < 4; i++) {
                float4 q = *(const float4*)&Qs[4 * ty + i][d];
                s[i][0] = fmaf(q.x, k0.x, fmaf(q.y, k0.y, fmaf(q.z, k0.z, fmaf(q.w, k0.w, s[i][0]))));
                s[i][1] = fmaf(q.x, k1.x, fmaf(q.y, k1.y, fmaf(q.z, k1.z, fmaf(q.w, k1.w, s[i][1]))));
            }
        }

        const int qrow0 = qt * 64 + 4 * ty;
        const int kcol0 = kt * 32 + 2 * tx;
#pragma unroll
        for (int i = 0; i < 4; i++) {
            if (kcol0     > qrow0 + i) s[i][0] = -1e30f;
            if (kcol0 + 1 > qrow0 + i) s[i][1] = -1e30f;

            float rm = fmaxf(s[i][0], s[i][1]);
#pragma unroll
            for (int off = 8; off >= 1; off >>= 1)
                rm = fmaxf(rm, __shfl_xor_sync(0xffffffffu, rm, off));

            float mnew = fmaxf(m_i[i], rm);
            float corr = __expf(m_i[i] - mnew);
            float p0 = __expf(s[i][0] - mnew);
            float p1 = __expf(s[i][1] - mnew);
            float ps = p0 + p1;
#pragma unroll
            for (int off = 8; off >= 1; off >>= 1)
                ps += __shfl_xor_sync(0xffffffffu, ps, off);

            l_i[i] = l_i[i] * corr + ps;
            m_i[i] = mnew;
#pragma unroll
            for (int j = 0; j < 4; j++) o[i][j] *= corr;

            Ps[4 * ty + i][2 * tx + 0] = p0;
            Ps[4 * ty + i][2 * tx + 1] = p1;
        }
        __syncthreads();

#pragma unroll 2
        for (int kk = 0; kk < 32; kk += 4) {
            float4 v0 = *(const float4*)&Vs[kk + 0][4 * tx];
            float4 v1 = *(const float4*)&Vs[kk + 1][4 * tx];
            float4 v2 = *(const float4*)&Vs[kk + 2][4 * tx];
            float4 v3 = *(const float4*)&Vs[kk + 3][4 * tx];
#pragma unroll
            for (int i = 0; i < 4; i++) {
                float4 p = *(const float4*)&Ps[4 * ty + i][kk];
                o[i][0] = fmaf(p.x, v0.x, fmaf(p.y, v1.x, fmaf(p.z, v2.x, fmaf(p.w, v3.x, o[i][0]))));
                o[i][1] = fmaf(p.x, v0.y, fmaf(p.y, v1.y, fmaf(p.z, v2.y, fmaf(p.w, v3.y, o[i][1]))));
                o[i][2] = fmaf(p.x, v0.z, fmaf(p.y, v1.z, fmaf(p.z, v2.z, fmaf(p.w, v3.z, o[i][2]))));
                o[i][3] = fmaf(p.x, v0.w, fmaf(p.y, v1.w, fmaf(p.z, v2.w, fmaf(p.w, v3.w, o[i][3]))));
            }
        }
    }

#pragma unroll
    for (int i = 0; i < 4; i++) {
        int row = qt * 64 + 4 * ty + i;
        float inv = 1.0f / l_i[i];
        float4 v = make_float4(o[i][0] * inv, o[i][1] * inv, o[i][2] * inv, o[i][3] * inv);
        *(float4*)(g_merged + (size_t)(b * SS + row) * DD + h * HDIM + 4 * tx) = v;
    }
}

// ---------------------------------------------------------------------------
extern "C" void kernel_launch(void* const* d_in, const int* in_sizes, int n_in,
                              void* d_out, int out_size) {
    const float* x    = (const float*)d_in[0];   // [B,S,D]
    const float* wqkv = (const float*)d_in[1];   // [D,3D]
    const float* wout = (const float*)d_in[2];   // [D,D]
    float*       out  = (float*)d_out;           // [B,S,D]

    __nv_bfloat16 *xhi, *xlo, *mhi, *mlo, *w1hi, *w1lo, *w2hi, *w2lo;
    float *merged, *qkv;
    cudaGetSymbolAddress((void**)&xhi, g_xhi);   cudaGetSymbolAddress((void**)&xlo, g_xlo);
    cudaGetSymbolAddress((void**)&mhi, g_mhi);   cudaGetSymbolAddress((void**)&mlo, g_mlo);
    cudaGetSymbolAddress((void**)&w1hi, g_w1hi); cudaGetSymbolAddress((void**)&w1lo, g_w1lo);
    cudaGetSymbolAddress((void**)&w2hi, g_w2hi); cudaGetSymbolAddress((void**)&w2lo, g_w2lo);
    cudaGetSymbolAddress((void**)&merged, g_merged);
    cudaGetSymbolAddress((void**)&qkv, g_qkv);

    cudaFuncSetAttribute(gemm_mma, cudaFuncAttributeMaxDynamicSharedMemorySize, GEMM_SMEM);

    // 1) split x and weights into bf16 hi/lo (weights keep [K][N] layout)
    {
        int n4 = MTOT * DD / 4;
        convert_split<<<(n4 + 255) / 256, 256>>>(x, xhi, xlo, n4);
        int w1 = DD * QKVN / 4;
        convert_split<<<(w1 + 255) / 256, 256>>>(wqkv, w1hi, w1lo, w1);
        int w2 = DD * DD / 4;
        convert_split<<<(w2 + 255) / 256, 256>>>(wout, w2hi, w2lo, w2);
    }
    // 2) QKV GEMM: [4096,1024] @ [1024,3072] on HMMA tensor cores
    gemm_mma<<<dim3(QKVN / 128, MTOT / 128), 256, GEMM_SMEM>>>(
        xhi, xlo, w1hi, w1lo, qkv, MTOT, QKVN, DD);
    // 3) attention
    flash_kernel<<<dim3(SS / 64, HH, BB), 256>>>();
    // 4) split merged
    {
        int n4 = MTOT * DD / 4;
        convert_split<<<(n4 + 255) / 256, 256>>>(merged, mhi, mlo, n4);
    }
    // 5) output GEMM: [4096,1024] @ [1024,1024]
    gemm_mma<<<dim3(DD / 128, MTOT / 128), 256, GEMM_SMEM>>>(
        mhi, mlo, w2hi, w2lo, out, MTOT, DD, DD);
}

// round 10
// speedup vs baseline: 2.8087x; 1.9581x over previous
#include <cuda_runtime.h>
#include <cuda_bf16.h>
#include <cstdint>

// ---------------------------------------------------------------------------
// MultiHeadSelfAttention, B=2, S=2048, D=1024, H=16, hd=64 (fp32 in/out).
// GEMMs AND flash attention on mma.sync.m16n8k16 bf16 with hi/lo split
// (fp32-class accuracy). Softmax exact fp32 on unscaled logits.
// R10: flash ported to HMMA (S=QK^T and O=PV on tensor pipe, in-register
// P->A-fragment conversion); QKV gemm + flash write bf16 hi/lo directly.
// ---------------------------------------------------------------------------

#define BB    2
#define SS    2048
#define DD    1024
#define HH    16
#define HDIM  64
#define QKVN  3072
#define MTOT  4096          // B*S

// Scratch (__device__ globals only; no allocations allowed)
__device__ __nv_bfloat16 g_qkvhi[(size_t)MTOT * QKVN], g_qkvlo[(size_t)MTOT * QKVN];
__device__ __nv_bfloat16 g_xhi[(size_t)MTOT * DD],  g_xlo[(size_t)MTOT * DD];
__device__ __nv_bfloat16 g_mhi[(size_t)MTOT * DD],  g_mlo[(size_t)MTOT * DD];
__device__ __nv_bfloat16 g_w1hi[(size_t)DD * QKVN], g_w1lo[(size_t)DD * QKVN];
__device__ __nv_bfloat16 g_w2hi[(size_t)DD * DD],   g_w2lo[(size_t)DD * DD];

// ---------------------------------------------------------------------------
// PTX helpers (all non-arch-specific; valid in compute_103 PTX)
// ---------------------------------------------------------------------------
__device__ __forceinline__ uint32_t smem_u32(const void* p) {
    uint32_t a;
    asm("{ .reg .u64 t; cvta.to.shared.u64 t, %1; cvt.u32.u64 %0, t; }" : "=r"(a) : "l"(p));
    return a;
}
__device__ __forceinline__ void cp_async16(uint32_t smem_dst, const void* gmem_src) {
    asm volatile("cp.async.cg.shared.global [%0], [%1], 16;" :: "r"(smem_dst), "l"(gmem_src));
}
__device__ __forceinline__ void cp_commit()   { asm volatile("cp.async.commit_group;"); }
__device__ __forceinline__ void cp_wait_all() { asm volatile("cp.async.wait_group 0;" ::: "memory"); }
__device__ __forceinline__ void cp_wait_1()   { asm volatile("cp.async.wait_group 1;" ::: "memory"); }

__device__ __forceinline__ void ldsm_x4(uint32_t* r, uint32_t addr) {
    asm volatile("ldmatrix.sync.aligned.m8n8.x4.shared.b16 {%0,%1,%2,%3}, [%4];"
                 : "=r"(r[0]), "=r"(r[1]), "=r"(r[2]), "=r"(r[3]) : "r"(addr));
}
__device__ __forceinline__ void ldsm_x4_t(uint32_t* r, uint32_t addr) {
    asm volatile("ldmatrix.sync.aligned.m8n8.x4.trans.shared.b16 {%0,%1,%2,%3}, [%4];"
                 : "=r"(r[0]), "=r"(r[1]), "=r"(r[2]), "=r"(r[3]) : "r"(addr));
}
__device__ __forceinline__ void mma_bf16(float* c, const uint32_t* a, const uint32_t* b) {
    asm volatile("mma.sync.aligned.m16n8k16.row.col.f32.bf16.bf16.f32 "
                 "{%0,%1,%2,%3}, {%4,%5,%6,%7}, {%8,%9}, {%0,%1,%2,%3};"
                 : "+f"(c[0]), "+f"(c[1]), "+f"(c[2]), "+f"(c[3])
                 : "r"(a[0]), "r"(a[1]), "r"(a[2]), "r"(a[3]), "r"(b[0]), "r"(b[1]));
}
__device__ __forceinline__ void mma_bf16_2(float* c, const uint32_t* a, uint32_t b0, uint32_t b1) {
    asm volatile("mma.sync.aligned.m16n8k16.row.col.f32.bf16.bf16.f32 "
                 "{%0,%1,%2,%3}, {%4,%5,%6,%7}, {%8,%9}, {%0,%1,%2,%3};"
                 : "+f"(c[0]), "+f"(c[1]), "+f"(c[2]), "+f"(c[3])
                 : "r"(a[0]), "r"(a[1]), "r"(a[2]), "r"(a[3]), "r"(b0), "r"(b1));
}

// pack two floats -> bf16x2 register (a -> low half, b -> high half)
__device__ __forceinline__ uint32_t pack_bf2(float a, float b) {
    __nv_bfloat162 v = __floats2bfloat162_rn(a, b);
    uint32_t u;
    memcpy(&u, &v, 4);
    return u;
}

// ---------------------------------------------------------------------------
// Split converts: v = hi + lo (two bf16, ~16 mantissa bits combined)
// ---------------------------------------------------------------------------
__device__ __forceinline__ void split1(float v, __nv_bfloat16& h, __nv_bfloat16& l) {
    h = __float2bfloat16(v);
    l = __float2bfloat16(v - __bfloat162float(h));
}

__global__ void convert_split(const float* __restrict__ src,
                              __nv_bfloat16* __restrict__ hi,
                              __nv_bfloat16* __restrict__ lo, int n4) {
    int i = blockIdx.x * blockDim.x + threadIdx.x;
    if (i >= n4) return;
    float4 v = ((const float4*)src)[i];
    __nv_bfloat16 h0, h1, h2, h3, l0, l1, l2, l3;
    split1(v.x, h0, l0); split1(v.y, h1, l1);
    split1(v.z, h2, l2); split1(v.w, h3, l3);
    __nv_bfloat162 a, b, c, d;
    a.x = h0; a.y = h1;  b.x = h2; b.y = h3;
    c.x = l0; c.y = l1;  d.x = l2; d.y = l3;
    ((__nv_bfloat162*)hi)[2 * i]     = a;
    ((__nv_bfloat162*)hi)[2 * i + 1] = b;
    ((__nv_bfloat162*)lo)[2 * i]     = c;
    ((__nv_bfloat162*)lo)[2 * i + 1] = d;
}

// ---------------------------------------------------------------------------
// bf16x3 split GEMM on mma.sync.  C[M,N] = A[M,K] @ B[K,N]  (row-major).
// CTA 128x128, BK=32, 8 warps (4m x 2n), warp tile 32x64, cp.async 2-stage.
// Output: fp32 C, or (if Chi != nullptr) bf16 hi/lo split pair.
// ---------------------------------------------------------------------------
#define A_PITCH 40
#define B_PITCH 136
#define A_BYTES (128 * A_PITCH * 2)
#define B_BYTES (32 * B_PITCH * 2)
#define STG_BYTES (2 * A_BYTES + 2 * B_BYTES)
#define OFF_AHI 0
#define OFF_ALO A_BYTES
#define OFF_BHI (2 * A_BYTES)
#define OFF_BLO (2 * A_BYTES + B_BYTES)
#define GEMM_SMEM (2 * STG_BYTES)

__global__ __launch_bounds__(256, 1)
void gemm_mma(const __nv_bfloat16* __restrict__ Ahi, const __nv_bfloat16* __restrict__ Alo,
              const __nv_bfloat16* __restrict__ Bhi, const __nv_bfloat16* __restrict__ Blo,
              float* __restrict__ C,
              __nv_bfloat16* __restrict__ Chi, __nv_bfloat16* __restrict__ Clo,
              int M, int N, int K) {
    extern __shared__ char smem[];
    const uint32_t sb = smem_u32(smem);

    const int t    = threadIdx.x;
    const int lane = t & 31;
    const int w    = t >> 5;
    const int wm   = w & 3;
    const int wn   = w >> 2;
    const int m0   = blockIdx.y * 128;
    const int n0   = blockIdx.x * 128;

    const int lr = lane & 15;
    const int lc = lane >> 4;

    float acc[2][8][4];
#pragma unroll
    for (int i = 0; i < 2; i++)
#pragma unroll
        for (int j = 0; j < 8; j++)
#pragma unroll
            for (int k = 0; k < 4; k++) acc[i][j][k] = 0.0f;

    const int KT = K >> 5;

#define LOAD_STAGE(s, buf)                                                       \
    do {                                                                         \
        const int _k0 = (s) << 5;                                                \
        const uint32_t _sB = sb + (uint32_t)(buf) * STG_BYTES;                   \
        _Pragma("unroll")                                                        \
        for (int j = 0; j < 2; j++) {                                            \
            int id = j * 256 + t;                                                \
            int r = id >> 2, kc = (id & 3) << 3;                                 \
            uint32_t o = (uint32_t)(r * (A_PITCH * 2) + kc * 2);                 \
            size_t g = (size_t)(m0 + r) * K + _k0 + kc;                          \
            cp_async16(_sB + OFF_AHI + o, Ahi + g);                              \
            cp_async16(_sB + OFF_ALO + o, Alo + g);                              \
        }                                                                        \
        _Pragma("unroll")                                                        \
        for (int j = 0; j < 2; j++) {                                            \
            int id = j * 256 + t;                                                \
            int r = id >> 4, nc = (id & 15) << 3;                                \
            uint32_t o = (uint32_t)(r * (B_PITCH * 2) + nc * 2);                 \
            size_t g = (size_t)(_k0 + r) * N + n0 + nc;                          \
            cp_async16(_sB + OFF_BHI + o, Bhi + g);                              \
            cp_async16(_sB + OFF_BLO + o, Blo + g);                              \
        }                                                                        \
    } while (0)

    LOAD_STAGE(0, 0);
    cp_commit();

    for (int s = 0; s < KT; s++) {
        const int buf = s & 1;
        cp_wait_all();
        __syncthreads();

        if (s + 1 < KT) {
            LOAD_STAGE(s + 1, buf ^ 1);
            cp_commit();
        }

        const uint32_t stg = sb + (uint32_t)buf * STG_BYTES;
#pragma unroll
        for (int ks = 0; ks < 2; ks++) {
            const int k16 = ks << 4;
            uint32_t ahi[2][4], alo[2][4], bhi[4][4], blo[4][4];
#pragma unroll
            for (int mi = 0; mi < 2; mi++) {
                uint32_t ao = (uint32_t)((wm * 32 + mi * 16 + lr) * (A_PITCH * 2)
                                         + (k16 + lc * 8) * 2);
                ldsm_x4(ahi[mi], stg + OFF_AHI + ao);
                ldsm_x4(alo[mi], stg + OFF_ALO + ao);
            }
#pragma unroll
            for (int g = 0; g < 4; g++) {
                uint32_t bo = (uint32_t)((k16 + lr) * (B_PITCH * 2)
                                         + (wn * 64 + g * 16 + lc * 8) * 2);
                ldsm_x4_t(bhi[g], stg + OFF_BHI + bo);
                ldsm_x4_t(blo[g], stg + OFF_BLO + bo);
            }
#pragma unroll
            for (int mi = 0; mi < 2; mi++)
#pragma unroll
                for (int g = 0; g < 4; g++) {
                    mma_bf16(acc[mi][g * 2 + 0], ahi[mi], &bhi[g][0]);
                    mma_bf16(acc[mi][g * 2 + 0], ahi[mi], &blo[g][0]);
                    mma_bf16(acc[mi][g * 2 + 0], alo[mi], &bhi[g][0]);
                    mma_bf16(acc[mi][g * 2 + 1], ahi[mi], &bhi[g][2]);
                    mma_bf16(acc[mi][g * 2 + 1], ahi[mi], &blo[g][2]);
                    mma_bf16(acc[mi][g * 2 + 1], alo[mi], &bhi[g][2]);
                }
        }
        __syncthreads();
    }
#undef LOAD_STAGE

    const int gq = lane >> 2;
    const int tq = lane & 3;
#pragma unroll
    for (int mi = 0; mi < 2; mi++)
#pragma unroll
        for (int nj = 0; nj < 8; nj++) {
            int row = m0 + wm * 32 + mi * 16 + gq;
            int col = n0 + wn * 64 + nj * 8 + tq * 2;
            if (Chi) {
                // bf16 hi/lo split output
                __nv_bfloat16 h0, h1, h2, h3, l0, l1, l2, l3;
                split1(acc[mi][nj][0], h0, l0); split1(acc[mi][nj][1], h1, l1);
                split1(acc[mi][nj][2], h2, l2); split1(acc[mi][nj][3], h3, l3);
                __nv_bfloat162 vh0; vh0.x = h0; vh0.y = h1;
                __nv_bfloat162 vl0; vl0.x = l0; vl0.y = l1;
                __nv_bfloat162 vh1; vh1.x = h2; vh1.y = h3;
                __nv_bfloat162 vl1; vl1.x = l2; vl1.y = l3;
                *(__nv_bfloat162*)(Chi + (size_t)row * N + col)       = vh0;
                *(__nv_bfloat162*)(Clo + (size_t)row * N + col)       = vl0;
                *(__nv_bfloat162*)(Chi + (size_t)(row + 8) * N + col) = vh1;
                *(__nv_bfloat162*)(Clo + (size_t)(row + 8) * N + col) = vl1;
            } else {
                float2 v0 = make_float2(acc[mi][nj][0], acc[mi][nj][1]);
                float2 v1 = make_float2(acc[mi][nj][2], acc[mi][nj][3]);
                *(float2*)(C + (size_t)row * N + col)       = v0;
                *(float2*)(C + (size_t)(row + 8) * N + col) = v1;
            }
        }
}

// ---------------------------------------------------------------------------
// Flash attention on mma.sync (bf16 hi/lo x3 for both QK^T and PV).
// Block = (qt, h, b): 64 q-rows, 4 warps x m16. K-tiles of 64 keys,
// cp.async double-buffered. Causal mask only on kt==qt. Online softmax in
// fp32 on fragment registers; P converted in-register to A-fragments.
// ---------------------------------------------------------------------------
#define FQ_PITCH 72                 // bf16 units per smem row
#define FQ_ROWB  (FQ_PITCH * 2)     // 144 bytes
#define FTILE_B  (64 * FQ_ROWB)     // 9216
#define OFF_QHI  0
#define OFF_QLO  FTILE_B
#define OFF_KVS  (2 * FTILE_B)      // stage base
#define KVSTG_B  (4 * FTILE_B)      // KHI,KLO,VHI,VLO per stage
#define FL_SMEM  (2 * FTILE_B + 2 * KVSTG_B)   // 92160

__device__ __forceinline__ void load_tile64(uint32_t sdst, const __nv_bfloat16* g, int t) {
#pragma unroll
    for (int j = 0; j < 4; j++) {
        int id = j * 128 + t;
        int r = id >> 3, c = id & 7;
        cp_async16(sdst + (uint32_t)(r * FQ_ROWB + c * 16), g + (size_t)r * QKVN + c * 8);
    }
}

__global__ __launch_bounds__(128) void flash_mma() {
    extern __shared__ char smem[];
    const uint32_t sb = smem_u32(smem);
    const int qt = (int)gridDim.x - 1 - (int)blockIdx.x;
    const int h  = blockIdx.y;
    const int b  = blockIdx.z;

    const int t    = threadIdx.x;
    const int lane = t & 31;
    const int w    = t >> 5;
    const int lr   = lane & 15;
    const int lc   = lane >> 4;
    const int gq   = lane >> 2;
    const int tq   = lane & 3;

    const size_t rowbase = (size_t)b * SS * QKVN + h * HDIM;

    // preamble: Q tile + K/V stage 0, one cp.async group
    load_tile64(sb + OFF_QHI, g_qkvhi + rowbase + (size_t)(qt * 64) * QKVN, t);
    load_tile64(sb + OFF_QLO, g_qkvlo + rowbase + (size_t)(qt * 64) * QKVN, t);
#define LOAD_KV(kt_, buf_)                                                           \
    do {                                                                             \
        const size_t kr = rowbase + DD + (size_t)((kt_) * 64) * QKVN;                \
        const uint32_t sd = sb + OFF_KVS + (uint32_t)(buf_) * KVSTG_B;               \
        load_tile64(sd,               g_qkvhi + kr, t);                              \
        load_tile64(sd + FTILE_B,     g_qkvlo + kr, t);                              \
        load_tile64(sd + 2 * FTILE_B, g_qkvhi + kr + DD, t);                         \
        load_tile64(sd + 3 * FTILE_B, g_qkvlo + kr + DD, t);                         \
    } while (0)
    LOAD_KV(0, 0);
    cp_commit();
    cp_wait_all();
    __syncthreads();

    // Q fragments (A operand, 4 k16 tiles)
    uint32_t qa_hi[4][4], qa_lo[4][4];
#pragma unroll
    for (int tk = 0; tk < 4; tk++) {
        uint32_t ao = (uint32_t)((w * 16 + lr) * FQ_ROWB + (tk * 16 + lc * 8) * 2);
        ldsm_x4(qa_hi[tk], sb + OFF_QHI + ao);
        ldsm_x4(qa_lo[tk], sb + OFF_QLO + ao);
    }

    float m_i[2] = {-1e30f, -1e30f};
    float l_i[2] = {0.0f, 0.0f};
    float o[8][4];
#pragma unroll
    for (int g = 0; g < 8; g++)
#pragma unroll
        for (int c = 0; c < 4; c++) o[g][c] = 0.0f;

    const int nkt = qt + 1;
    for (int kt = 0; kt < nkt; kt++) {
        const int buf = kt & 1;
        const uint32_t stg = sb + OFF_KVS + (uint32_t)buf * KVSTG_B;

        if (kt + 1 < nkt) {
            LOAD_KV(kt + 1, buf ^ 1);
            cp_commit();
            cp_wait_1();
        } else {
            cp_wait_all();
        }
        __syncthreads();

        // ---- S = Q @ K^T : s[8 key-n8-tiles][4]
        float s[8][4];
#pragma unroll
        for (int g = 0; g < 8; g++)
#pragma unroll
            for (int c = 0; c < 4; c++) s[g][c] = 0.0f;
#pragma unroll
        for (int tk = 0; tk < 4; tk++) {
            uint32_t kbh[4][4], kbl[4][4];
#pragma unroll
            for (int j = 0; j < 4; j++) {
                uint32_t ao = (uint32_t)((j * 16 + lr) * FQ_ROWB + (tk * 16 + lc * 8) * 2);
                ldsm_x4(kbh[j], stg + ao);
                ldsm_x4(kbl[j], stg + FTILE_B + ao);
            }
#pragma unroll
            for (int j = 0; j < 4; j++) {
                // non-trans x4 from [key][d]: r0=n0-7/k0-7, r1=n8-15/k0-7,
                // r2=n0-7/k8-15, r3=n8-15/k8-15 -> tile 2j: (r0,r2); 2j+1: (r1,r3)
                mma_bf16_2(s[2 * j],     qa_hi[tk], kbh[j][0], kbh[j][2]);
                mma_bf16_2(s[2 * j],     qa_hi[tk], kbl[j][0], kbl[j][2]);
                mma_bf16_2(s[2 * j],     qa_lo[tk], kbh[j][0], kbh[j][2]);
                mma_bf16_2(s[2 * j + 1], qa_hi[tk], kbh[j][1], kbh[j][3]);
                mma_bf16_2(s[2 * j + 1], qa_hi[tk], kbl[j][1], kbl[j][3]);
                mma_bf16_2(s[2 * j + 1], qa_lo[tk], kbh[j][1], kbh[j][3]);
            }
        }

        // ---- causal mask (diagonal tile only)
        const int row0 = qt * 64 + w * 16 + gq;
        if (kt == qt) {
#pragma unroll
            for (int g = 0; g < 8; g++) {
                int col = kt * 64 + g * 8 + tq * 2;
                if (col     > row0)     s[g][0] = -1e30f;
                if (col + 1 > row0)     s[g][1] = -1e30f;
                if (col     > row0 + 8) s[g][2] = -1e30f;
                if (col + 1 > row0 + 8) s[g][3] = -1e30f;
            }
        }

        // ---- online softmax (rows gq, gq+8; quad shuffles reduce the row)
        float mx0 = -1e30f, mx1 = -1e30f;
#pragma unroll
        for (int g = 0; g < 8; g++) {
            mx0 = fmaxf(mx0, fmaxf(s[g][0], s[g][1]));
            mx1 = fmaxf(mx1, fmaxf(s[g][2], s[g][3]));
        }
#pragma unroll
        for (int off = 1; off <= 2; off <<= 1) {
            mx0 = fmaxf(mx0, __shfl_xor_sync(0xffffffffu, mx0, off));
            mx1 = fmaxf(mx1, __shfl_xor_sync(0xffffffffu, mx1, off));
        }
        const float mnew0 = fmaxf(m_i[0], mx0);
        const float mnew1 = fmaxf(m_i[1], mx1);
        const float corr0 = __expf(m_i[0] - mnew0);
        const float corr1 = __expf(m_i[1] - mnew1);

        float ps0 = 0.0f, ps1 = 0.0f;
        uint32_t pa_hi[4][4], pa_lo[4][4];
#pragma unroll
        for (int g = 0; g < 8; g++) {
            float p0 = __expf(s[g][0] - mnew0);
            float p1 = __expf(s[g][1] - mnew0);
            float p2 = __expf(s[g][2] - mnew1);
            float p3 = __expf(s[g][3] - mnew1);
            ps0 += p0 + p1;
            ps1 += p2 + p3;
            // split p = hi + lo, pack into A-fragment slots
            __nv_bfloat16 h0 = __float2bfloat16(p0), h1 = __float2bfloat16(p1);
            __nv_bfloat16 h2 = __float2bfloat16(p2), h3 = __float2bfloat16(p3);
            float r0f = p0 - __bfloat162float(h0), r1f = p1 - __bfloat162float(h1);
            float r2f = p2 - __bfloat162float(h2), r3f = p3 - __bfloat162float(h3);
            __nv_bfloat162 ph0; ph0.x = h0; ph0.y = h1;
            __nv_bfloat162 ph1; ph1.x = h2; ph1.y = h3;
            uint32_t uh0, uh1;
            memcpy(&uh0, &ph0, 4); memcpy(&uh1, &ph1, 4);
            int tk2 = g >> 1, odd = g & 1;
            pa_hi[tk2][odd * 2 + 0] = uh0;       // rows gq   (a0/a2)
            pa_hi[tk2][odd * 2 + 1] = uh1;       // rows gq+8 (a1/a3)
            pa_lo[tk2][odd * 2 + 0] = pack_bf2(r0f, r1f);
            pa_lo[tk2][odd * 2 + 1] = pack_bf2(r2f, r3f);
        }
#pragma unroll
        for (int off = 1; off <= 2; off <<= 1) {
            ps0 += __shfl_xor_sync(0xffffffffu, ps0, off);
            ps1 += __shfl_xor_sync(0xffffffffu, ps1, off);
        }
        l_i[0] = l_i[0] * corr0 + ps0;
        l_i[1] = l_i[1] * corr1 + ps1;
        m_i[0] = mnew0;
        m_i[1] = mnew1;
#pragma unroll
        for (int g = 0; g < 8; g++) {
            o[g][0] *= corr0; o[g][1] *= corr0;
            o[g][2] *= corr1; o[g][3] *= corr1;
        }

        // ---- O += P @ V : V[key][d] via trans ldmatrix (GEMM-B pattern)
#pragma unroll
        for (int tk = 0; tk < 4; tk++) {       // k16 over keys
            uint32_t vbh[4][4], vbl[4][4];
#pragma unroll
            for (int j = 0; j < 4; j++) {      // 16-wide d blocks
                uint32_t ao = (uint32_t)((tk * 16 + lr) * FQ_ROWB + (j * 16 + lc * 8) * 2);
                ldsm_x4_t(vbh[j], stg + 2 * FTILE_B + ao);
                ldsm_x4_t(vbl[j], stg + 3 * FTILE_B + ao);
            }
#pragma unroll
            for (int j = 0; j < 4; j++) {
                mma_bf16(o[2 * j],     pa_hi[tk], &vbh[j][0]);
                mma_bf16(o[2 * j],     pa_hi[tk], &vbl[j][0]);
                mma_bf16(o[2 * j],     pa_lo[tk], &vbh[j][0]);
                mma_bf16(o[2 * j + 1], pa_hi[tk], &vbh[j][2]);
                mma_bf16(o[2 * j + 1], pa_hi[tk], &vbl[j][2]);
                mma_bf16(o[2 * j + 1], pa_lo[tk], &vbh[j][2]);
            }
        }
        __syncthreads();   // all warps done with this stage before it is reused
    }
#undef LOAD_KV

    // ---- epilogue: normalize and write merged as bf16 hi/lo
    const float inv0 = 1.0f / l_i[0];
    const float inv1 = 1.0f / l_i[1];
    const int row0 = qt * 64 + w * 16 + gq;
    const size_t base0 = (size_t)(b * SS + row0) * DD + h * HDIM;
    const size_t base1 = base0 + (size_t)8 * DD;
#pragma unroll
    for (int g = 0; g < 8; g++) {
        int col = g * 8 + tq * 2;
        float v0 = o[g][0] * inv0, v1 = o[g][1] * inv0;
        float v2 = o[g][2] * inv1, v3 = o[g][3] * inv1;
        __nv_bfloat16 h0, h1, h2, h3, l0, l1, l2, l3;
        split1(v0, h0, l0); split1(v1, h1, l1);
        split1(v2, h2, l2); split1(v3, h3, l3);
        __nv_bfloat162 ph0; ph0.x = h0; ph0.y = h1;
        __nv_bfloat162 pl0; pl0.x = l0; pl0.y = l1;
        __nv_bfloat162 ph1; ph1.x = h2; ph1.y = h3;
        __nv_bfloat162 pl1; pl1.x = l2; pl1.y = l3;
        *(__nv_bfloat162*)(g_mhi + base0 + col) = ph0;
        *(__nv_bfloat162*)(g_mlo + base0 + col) = pl0;
        *(__nv_bfloat162*)(g_mhi + base1 + col) = ph1;
        *(__nv_bfloat162*)(g_mlo + base1 + col) = pl1;
    }
}

// ---------------------------------------------------------------------------
extern "C" void kernel_launch(void* const* d_in, const int* in_sizes, int n_in,
                              void* d_out, int out_size) {
    const float* x    = (const float*)d_in[0];   // [B,S,D]
    const float* wqkv = (const float*)d_in[1];   // [D,3D]
    const float* wout = (const float*)d_in[2];   // [D,D]
    float*       out  = (float*)d_out;           // [B,S,D]

    __nv_bfloat16 *xhi, *xlo, *mhi, *mlo, *w1hi, *w1lo, *w2hi, *w2lo, *qhi, *qlo;
    cudaGetSymbolAddress((void**)&xhi, g_xhi);   cudaGetSymbolAddress((void**)&xlo, g_xlo);
    cudaGetSymbolAddress((void**)&mhi, g_mhi);   cudaGetSymbolAddress((void**)&mlo, g_mlo);
    cudaGetSymbolAddress((void**)&w1hi, g_w1hi); cudaGetSymbolAddress((void**)&w1lo, g_w1lo);
    cudaGetSymbolAddress((void**)&w2hi, g_w2hi); cudaGetSymbolAddress((void**)&w2lo, g_w2lo);
    cudaGetSymbolAddress((void**)&qhi, g_qkvhi); cudaGetSymbolAddress((void**)&qlo, g_qkvlo);

    cudaFuncSetAttribute(gemm_mma, cudaFuncAttributeMaxDynamicSharedMemorySize, GEMM_SMEM);
    cudaFuncSetAttribute(flash_mma, cudaFuncAttributeMaxDynamicSharedMemorySize, FL_SMEM);

    // 1) split inputs to bf16 hi/lo
    {
        int n4 = MTOT * DD / 4;
        convert_split<<<(n4 + 255) / 256, 256>>>(x, xhi, xlo, n4);
        int w1 = DD * QKVN / 4;
        convert_split<<<(w1 + 255) / 256, 256>>>(wqkv, w1hi, w1lo, w1);
        int w2 = DD * DD / 4;
        convert_split<<<(w2 + 255) / 256, 256>>>(wout, w2hi, w2lo, w2);
    }
    // 2) QKV GEMM -> bf16 hi/lo split output (consumed by flash)
    gemm_mma<<<dim3(QKVN / 128, MTOT / 128), 256, GEMM_SMEM>>>(
        xhi, xlo, w1hi, w1lo, nullptr, qhi, qlo, MTOT, QKVN, DD);
    // 3) flash attention on tensor cores -> merged bf16 hi/lo
    flash_mma<<<dim3(SS / 64, HH, BB), 128, FL_SMEM>>>();
    // 4) output GEMM -> fp32 out
    gemm_mma<<<dim3(DD / 128, MTOT / 128), 256, GEMM_SMEM>>>(
        mhi, mlo, w2hi, w2lo, out, nullptr, nullptr, MTOT, DD, DD);
}

// round 12
// speedup vs baseline: 3.1832x; 1.1333x over previous
#include <cuda_runtime.h>
#include <cuda_bf16.h>
#include <cstdint>

// ---------------------------------------------------------------------------
// MultiHeadSelfAttention, B=2, S=2048, D=1024, H=16, hd=64 (fp32 in/out).
// GEMMs AND flash attention on mma.sync.m16n8k16 bf16 with hi/lo split
// (fp32-class accuracy). Softmax exact fp32 on unscaled logits.
// R11/R12: gemm_mma -> __launch_bounds__(256,2) (2 CTAs/SM, regs capped 128)
// with B-fragments loaded in two halves to cut register liveness.
// ---------------------------------------------------------------------------

#define BB    2
#define SS    2048
#define DD    1024
#define HH    16
#define HDIM  64
#define QKVN  3072
#define MTOT  4096          // B*S

// Scratch (__device__ globals only; no allocations allowed)
__device__ __nv_bfloat16 g_qkvhi[(size_t)MTOT * QKVN], g_qkvlo[(size_t)MTOT * QKVN];
__device__ __nv_bfloat16 g_xhi[(size_t)MTOT * DD],  g_xlo[(size_t)MTOT * DD];
__device__ __nv_bfloat16 g_mhi[(size_t)MTOT * DD],  g_mlo[(size_t)MTOT * DD];
__device__ __nv_bfloat16 g_w1hi[(size_t)DD * QKVN], g_w1lo[(size_t)DD * QKVN];
__device__ __nv_bfloat16 g_w2hi[(size_t)DD * DD],   g_w2lo[(size_t)DD * DD];

// ---------------------------------------------------------------------------
// PTX helpers (all non-arch-specific; valid in compute_103 PTX)
// ---------------------------------------------------------------------------
__device__ __forceinline__ uint32_t smem_u32(const void* p) {
    uint32_t a;
    asm("{ .reg .u64 t; cvta.to.shared.u64 t, %1; cvt.u32.u64 %0, t; }" : "=r"(a) : "l"(p));
    return a;
}
__device__ __forceinline__ void cp_async16(uint32_t smem_dst, const void* gmem_src) {
    asm volatile("cp.async.cg.shared.global [%0], [%1], 16;" :: "r"(smem_dst), "l"(gmem_src));
}
__device__ __forceinline__ void cp_commit()   { asm volatile("cp.async.commit_group;"); }
__device__ __forceinline__ void cp_wait_all() { asm volatile("cp.async.wait_group 0;" ::: "memory"); }
__device__ __forceinline__ void cp_wait_1()   { asm volatile("cp.async.wait_group 1;" ::: "memory"); }

__device__ __forceinline__ void ldsm_x4(uint32_t* r, uint32_t addr) {
    asm volatile("ldmatrix.sync.aligned.m8n8.x4.shared.b16 {%0,%1,%2,%3}, [%4];"
                 : "=r"(r[0]), "=r"(r[1]), "=r"(r[2]), "=r"(r[3]) : "r"(addr));
}
__device__ __forceinline__ void ldsm_x4_t(uint32_t* r, uint32_t addr) {
    asm volatile("ldmatrix.sync.aligned.m8n8.x4.trans.shared.b16 {%0,%1,%2,%3}, [%4];"
                 : "=r"(r[0]), "=r"(r[1]), "=r"(r[2]), "=r"(r[3]) : "r"(addr));
}
__device__ __forceinline__ void mma_bf16(float* c, const uint32_t* a, const uint32_t* b) {
    asm volatile("mma.sync.aligned.m16n8k16.row.col.f32.bf16.bf16.f32 "
                 "{%0,%1,%2,%3}, {%4,%5,%6,%7}, {%8,%9}, {%0,%1,%2,%3};"
                 : "+f"(c[0]), "+f"(c[1]), "+f"(c[2]), "+f"(c[3])
                 : "r"(a[0]), "r"(a[1]), "r"(a[2]), "r"(a[3]), "r"(b[0]), "r"(b[1]));
}
__device__ __forceinline__ void mma_bf16_2(float* c, const uint32_t* a, uint32_t b0, uint32_t b1) {
    asm volatile("mma.sync.aligned.m16n8k16.row.col.f32.bf16.bf16.f32 "
                 "{%0,%1,%2,%3}, {%4,%5,%6,%7}, {%8,%9}, {%0,%1,%2,%3};"
                 : "+f"(c[0]), "+f"(c[1]), "+f"(c[2]), "+f"(c[3])
                 : "r"(a[0]), "r"(a[1]), "r"(a[2]), "r"(a[3]), "r"(b0), "r"(b1));
}

// pack two floats -> bf16x2 register (a -> low half, b -> high half)
__device__ __forceinline__ uint32_t pack_bf2(float a, float b) {
    __nv_bfloat162 v = __floats2bfloat162_rn(a, b);
    uint32_t u;
    memcpy(&u, &v, 4);
    return u;
}

// ---------------------------------------------------------------------------
// Split converts: v = hi + lo (two bf16, ~16 mantissa bits combined)
// ---------------------------------------------------------------------------
__device__ __forceinline__ void split1(float v, __nv_bfloat16& h, __nv_bfloat16& l) {
    h = __float2bfloat16(v);
    l = __float2bfloat16(v - __bfloat162float(h));
}

__global__ void convert_split(const float* __restrict__ src,
                              __nv_bfloat16* __restrict__ hi,
                              __nv_bfloat16* __restrict__ lo, int n4) {
    int i = blockIdx.x * blockDim.x + threadIdx.x;
    if (i >= n4) return;
    float4 v = ((const float4*)src)[i];
    __nv_bfloat16 h0, h1, h2, h3, l0, l1, l2, l3;
    split1(v.x, h0, l0); split1(v.y, h1, l1);
    split1(v.z, h2, l2); split1(v.w, h3, l3);
    __nv_bfloat162 a, b, c, d;
    a.x = h0; a.y = h1;  b.x = h2; b.y = h3;
    c.x = l0; c.y = l1;  d.x = l2; d.y = l3;
    ((__nv_bfloat162*)hi)[2 * i]     = a;
    ((__nv_bfloat162*)hi)[2 * i + 1] = b;
    ((__nv_bfloat162*)lo)[2 * i]     = c;
    ((__nv_bfloat162*)lo)[2 * i + 1] = d;
}

// ---------------------------------------------------------------------------
// bf16x3 split GEMM on mma.sync.  C[M,N] = A[M,K] @ B[K,N]  (row-major).
// CTA 128x128, BK=32, 8 warps (4m x 2n), warp tile 32x64, cp.async 2-stage.
// 2 CTAs/SM (launch_bounds(256,2)); B fragments loaded in two halves.
// Output: fp32 C, or (if Chi != nullptr) bf16 hi/lo split pair.
// ---------------------------------------------------------------------------
#define A_PITCH 40
#define B_PITCH 136
#define A_BYTES (128 * A_PITCH * 2)
#define B_BYTES (32 * B_PITCH * 2)
#define STG_BYTES (2 * A_BYTES + 2 * B_BYTES)
#define OFF_AHI 0
#define OFF_ALO A_BYTES
#define OFF_BHI (2 * A_BYTES)
#define OFF_BLO (2 * A_BYTES + B_BYTES)
#define GEMM_SMEM (2 * STG_BYTES)

__global__ __launch_bounds__(256, 2)
void gemm_mma(const __nv_bfloat16* __restrict__ Ahi, const __nv_bfloat16* __restrict__ Alo,
              const __nv_bfloat16* __restrict__ Bhi, const __nv_bfloat16* __restrict__ Blo,
              float* __restrict__ C,
              __nv_bfloat16* __restrict__ Chi, __nv_bfloat16* __restrict__ Clo,
              int M, int N, int K) {
    extern __shared__ char smem[];
    const uint32_t sb = smem_u32(smem);

    const int t    = threadIdx.x;
    const int lane = t & 31;
    const int w    = t >> 5;
    const int wm   = w & 3;
    const int wn   = w >> 2;
    const int m0   = blockIdx.y * 128;
    const int n0   = blockIdx.x * 128;

    const int lr = lane & 15;
    const int lc = lane >> 4;

    float acc[2][8][4];
#pragma unroll
    for (int i = 0; i < 2; i++)
#pragma unroll
        for (int j = 0; j < 8; j++)
#pragma unroll
            for (int k = 0; k < 4; k++) acc[i][j][k] = 0.0f;

    const int KT = K >> 5;

#define LOAD_STAGE(s, buf)                                                       \
    do {                                                                         \
        const int _k0 = (s) << 5;                                                \
        const uint32_t _sB = sb + (uint32_t)(buf) * STG_BYTES;                   \
        _Pragma("unroll")                                                        \
        for (int j = 0; j < 2; j++) {                                            \
            int id = j * 256 + t;                                                \
            int r = id >> 2, kc = (id & 3) << 3;                                 \
            uint32_t o = (uint32_t)(r * (A_PITCH * 2) + kc * 2);                 \
            size_t g = (size_t)(m0 + r) * K + _k0 + kc;                          \
            cp_async16(_sB + OFF_AHI + o, Ahi + g);                              \
            cp_async16(_sB + OFF_ALO + o, Alo + g);                              \
        }                                                                        \
        _Pragma("unroll")                                                        \
        for (int j = 0; j < 2; j++) {                                            \
            int id = j * 256 + t;                                                \
            int r = id >> 4, nc = (id & 15) << 3;                                \
            uint32_t o = (uint32_t)(r * (B_PITCH * 2) + nc * 2);                 \
            size_t g = (size_t)(_k0 + r) * N + n0 + nc;                          \
            cp_async16(_sB + OFF_BHI + o, Bhi + g);                              \
            cp_async16(_sB + OFF_BLO + o, Blo + g);                              \
        }                                                                        \
    } while (0)

    LOAD_STAGE(0, 0);
    cp_commit();

    for (int s = 0; s < KT; s++) {
        const int buf = s & 1;
        cp_wait_all();
        __syncthreads();

        if (s + 1 < KT) {
            LOAD_STAGE(s + 1, buf ^ 1);
            cp_commit();
        }

        const uint32_t stg = sb + (uint32_t)buf * STG_BYTES;
#pragma unroll
        for (int ks = 0; ks < 2; ks++) {
            const int k16 = ks << 4;
            uint32_t ahi[2][4], alo[2][4];
#pragma unroll
            for (int mi = 0; mi < 2; mi++) {
                uint32_t ao = (uint32_t)((wm * 32 + mi * 16 + lr) * (A_PITCH * 2)
                                         + (k16 + lc * 8) * 2);
                ldsm_x4(ahi[mi], stg + OFF_AHI + ao);
                ldsm_x4(alo[mi], stg + OFF_ALO + ao);
            }
            // B fragments in two halves (g: 0-1, then 2-3) to cut liveness
#pragma unroll
            for (int gh = 0; gh < 2; gh++) {
                uint32_t bhi[2][4], blo[2][4];
#pragma unroll
                for (int g2 = 0; g2 < 2; g2++) {
                    int g = gh * 2 + g2;
                    uint32_t bo = (uint32_t)((k16 + lr) * (B_PITCH * 2)
                                             + (wn * 64 + g * 16 + lc * 8) * 2);
                    ldsm_x4_t(bhi[g2], stg + OFF_BHI + bo);
                    ldsm_x4_t(blo[g2], stg + OFF_BLO + bo);
                }
#pragma unroll
                for (int mi = 0; mi < 2; mi++)
#pragma unroll
                    for (int g2 = 0; g2 < 2; g2++) {
                        int g = gh * 2 + g2;
                        mma_bf16(acc[mi][g * 2 + 0], ahi[mi], &bhi[g2][0]);
                        mma_bf16(acc[mi][g * 2 + 0], ahi[mi], &blo[g2][0]);
                        mma_bf16(acc[mi][g * 2 + 0], alo[mi], &bhi[g2][0]);
                        mma_bf16(acc[mi][g * 2 + 1], ahi[mi], &bhi[g2][2]);
                        mma_bf16(acc[mi][g * 2 + 1], ahi[mi], &blo[g2][2]);
                        mma_bf16(acc[mi][g * 2 + 1], alo[mi], &bhi[g2][2]);
                    }
            }
        }
        __syncthreads();
    }
#undef LOAD_STAGE

    const int gq = lane >> 2;
    const int tq = lane & 3;
#pragma unroll
    for (int mi = 0; mi < 2; mi++)
#pragma unroll
        for (int nj = 0; nj < 8; nj++) {
            int row = m0 + wm * 32 + mi * 16 + gq;
            int col = n0 + wn * 64 + nj * 8 + tq * 2;
            if (Chi) {
                __nv_bfloat16 h0, h1, h2, h3, l0, l1, l2, l3;
                split1(acc[mi][nj][0], h0, l0); split1(acc[mi][nj][1], h1, l1);
                split1(acc[mi][nj][2], h2, l2); split1(acc[mi][nj][3], h3, l3);
                __nv_bfloat162 vh0; vh0.x = h0; vh0.y = h1;
                __nv_bfloat162 vl0; vl0.x = l0; vl0.y = l1;
                __nv_bfloat162 vh1; vh1.x = h2; vh1.y = h3;
                __nv_bfloat162 vl1; vl1.x = l2; vl1.y = l3;
                *(__nv_bfloat162*)(Chi + (size_t)row * N + col)       = vh0;
                *(__nv_bfloat162*)(Clo + (size_t)row * N + col)       = vl0;
                *(__nv_bfloat162*)(Chi + (size_t)(row + 8) * N + col) = vh1;
                *(__nv_bfloat162*)(Clo + (size_t)(row + 8) * N + col) = vl1;
            } else {
                float2 v0 = make_float2(acc[mi][nj][0], acc[mi][nj][1]);
                float2 v1 = make_float2(acc[mi][nj][2], acc[mi][nj][3]);
                *(float2*)(C + (size_t)row * N + col)       = v0;
                *(float2*)(C + (size_t)(row + 8) * N + col) = v1;
            }
        }
}

// ---------------------------------------------------------------------------
// Flash attention on mma.sync (bf16 hi/lo x3 for both QK^T and PV).
// Block = (qt, h, b): 64 q-rows, 4 warps x m16. K-tiles of 64 keys,
// cp.async double-buffered. Causal mask only on kt==qt. Online softmax in
// fp32 on fragment registers; P converted in-register to A-fragments.
// (unchanged from R10 -- hardware-validated)
// ---------------------------------------------------------------------------
#define FQ_PITCH 72                 // bf16 units per smem row
#define FQ_ROWB  (FQ_PITCH * 2)     // 144 bytes
#define FTILE_B  (64 * FQ_ROWB)     // 9216
#define OFF_QHI  0
#define OFF_QLO  FTILE_B
#define OFF_KVS  (2 * FTILE_B)      // stage base
#define KVSTG_B  (4 * FTILE_B)      // KHI,KLO,VHI,VLO per stage
#define FL_SMEM  (2 * FTILE_B + 2 * KVSTG_B)   // 92160

__device__ __forceinline__ void load_tile64(uint32_t sdst, const __nv_bfloat16* g, int t) {
#pragma unroll
    for (int j = 0; j < 4; j++) {
        int id = j * 128 + t;
        int r = id >> 3, c = id & 7;
        cp_async16(sdst + (uint32_t)(r * FQ_ROWB + c * 16), g + (size_t)r * QKVN + c * 8);
    }
}

__global__ __launch_bounds__(128) void flash_mma() {
    extern __shared__ char smem[];
    const uint32_t sb = smem_u32(smem);
    const int qt = (int)gridDim.x - 1 - (int)blockIdx.x;
    const int h  = blockIdx.y;
    const int b  = blockIdx.z;

    const int t    = threadIdx.x;
    const int lane = t & 31;
    const int w    = t >> 5;
    const int lr   = lane & 15;
    const int lc   = lane >> 4;
    const int gq   = lane >> 2;
    const int tq   = lane & 3;

    const size_t rowbase = (size_t)b * SS * QKVN + h * HDIM;

    load_tile64(sb + OFF_QHI, g_qkvhi + rowbase + (size_t)(qt * 64) * QKVN, t);
    load_tile64(sb + OFF_QLO, g_qkvlo + rowbase + (size_t)(qt * 64) * QKVN, t);
#define LOAD_KV(kt_, buf_)                                                           \
    do {                                                                             \
        const size_t kr = rowbase + DD + (size_t)((kt_) * 64) * QKVN;                \
        const uint32_t sd = sb + OFF_KVS + (uint32_t)(buf_) * KVSTG_B;               \
        load_tile64(sd,               g_qkvhi + kr, t);                              \
        load_tile64(sd + FTILE_B,     g_qkvlo + kr, t);                              \
        load_tile64(sd + 2 * FTILE_B, g_qkvhi + kr + DD, t);                         \
        load_tile64(sd + 3 * FTILE_B, g_qkvlo + kr + DD, t);                         \
    } while (0)
    LOAD_KV(0, 0);
    cp_commit();
    cp_wait_all();
    __syncthreads();

    uint32_t qa_hi[4][4], qa_lo[4][4];
#pragma unroll
    for (int tk = 0; tk < 4; tk++) {
        uint32_t ao = (uint32_t)((w * 16 + lr) * FQ_ROWB + (tk * 16 + lc * 8) * 2);
        ldsm_x4(qa_hi[tk], sb + OFF_QHI + ao);
        ldsm_x4(qa_lo[tk], sb + OFF_QLO + ao);
    }

    float m_i[2] = {-1e30f, -1e30f};
    float l_i[2] = {0.0f, 0.0f};
    float o[8][4];
#pragma unroll
    for (int g = 0; g < 8; g++)
#pragma unroll
        for (int c = 0; c < 4; c++) o[g][c] = 0.0f;

    const int nkt = qt + 1;
    for (int kt = 0; kt < nkt; kt++) {
        const int buf = kt & 1;
        const uint32_t stg = sb + OFF_KVS + (uint32_t)buf * KVSTG_B;

        if (kt + 1 < nkt) {
            LOAD_KV(kt + 1, buf ^ 1);
            cp_commit();
            cp_wait_1();
        } else {
            cp_wait_all();
        }
        __syncthreads();

        float s[8][4];
#pragma unroll
        for (int g = 0; g < 8; g++)
#pragma unroll
            for (int c = 0; c < 4; c++) s[g][c] = 0.0f;
#pragma unroll
        for (int tk = 0; tk < 4; tk++) {
            uint32_t kbh[4][4], kbl[4][4];
#pragma unroll
            for (int j = 0; j < 4; j++) {
                uint32_t ao = (uint32_t)((j * 16 + lr) * FQ_ROWB + (tk * 16 + lc * 8) * 2);
                ldsm_x4(kbh[j], stg + ao);
                ldsm_x4(kbl[j], stg + FTILE_B + ao);
            }
#pragma unroll
            for (int j = 0; j < 4; j++) {
                mma_bf16_2(s[2 * j],     qa_hi[tk], kbh[j][0], kbh[j][2]);
                mma_bf16_2(s[2 * j],     qa_hi[tk], kbl[j][0], kbl[j][2]);
                mma_bf16_2(s[2 * j],     qa_lo[tk], kbh[j][0], kbh[j][2]);
                mma_bf16_2(s[2 * j + 1], qa_hi[tk], kbh[j][1], kbh[j][3]);
                mma_bf16_2(s[2 * j + 1], qa_hi[tk], kbl[j][1], kbl[j][3]);
                mma_bf16_2(s[2 * j + 1], qa_lo[tk], kbh[j][1], kbh[j][3]);
            }
        }

        const int row0 = qt * 64 + w * 16 + gq;
        if (kt == qt) {
#pragma unroll
            for (int g = 0; g < 8; g++) {
                int col = kt * 64 + g * 8 + tq * 2;
                if (col     > row0)     s[g][0] = -1e30f;
                if (col + 1 > row0)     s[g][1] = -1e30f;
                if (col     > row0 + 8) s[g][2] = -1e30f;
                if (col + 1 > row0 + 8) s[g][3] = -1e30f;
            }
        }

        float mx0 = -1e30f, mx1 = -1e30f;
#pragma unroll
        for (int g = 0; g < 8; g++) {
            mx0 = fmaxf(mx0, fmaxf(s[g][0], s[g][1]));
            mx1 = fmaxf(mx1, fmaxf(s[g][2], s[g][3]));
        }
#pragma unroll
        for (int off = 1; off <= 2; off <<= 1) {
            mx0 = fmaxf(mx0, __shfl_xor_sync(0xffffffffu, mx0, off));
            mx1 = fmaxf(mx1, __shfl_xor_sync(0xffffffffu, mx1, off));
        }
        const float mnew0 = fmaxf(m_i[0], mx0);
        const float mnew1 = fmaxf(m_i[1], mx1);
        const float corr0 = __expf(m_i[0] - mnew0);
        const float corr1 = __expf(m_i[1] - mnew1);

        float ps0 = 0.0f, ps1 = 0.0f;
        uint32_t pa_hi[4][4], pa_lo[4][4];
#pragma unroll
        for (int g = 0; g < 8; g++) {
            float p0 = __expf(s[g][0] - mnew0);
            float p1 = __expf(s[g][1] - mnew0);
            float p2 = __expf(s[g][2] - mnew1);
            float p3 = __expf(s[g][3] - mnew1);
            ps0 += p0 + p1;
            ps1 += p2 + p3;
            __nv_bfloat16 h0 = __float2bfloat16(p0), h1 = __float2bfloat16(p1);
            __nv_bfloat16 h2 = __float2bfloat16(p2), h3 = __float2bfloat16(p3);
            float r0f = p0 - __bfloat162float(h0), r1f = p1 - __bfloat162float(h1);
            float r2f = p2 - __bfloat162float(h2), r3f = p3 - __bfloat162float(h3);
            __nv_bfloat162 ph0; ph0.x = h0; ph0.y = h1;
            __nv_bfloat162 ph1; ph1.x = h2; ph1.y = h3;
            uint32_t uh0, uh1;
            memcpy(&uh0, &ph0, 4); memcpy(&uh1, &ph1, 4);
            int tk2 = g >> 1, odd = g & 1;
            pa_hi[tk2][odd * 2 + 0] = uh0;
            pa_hi[tk2][odd * 2 + 1] = uh1;
            pa_lo[tk2][odd * 2 + 0] = pack_bf2(r0f, r1f);
            pa_lo[tk2][odd * 2 + 1] = pack_bf2(r2f, r3f);
        }
#pragma unroll
        for (int off = 1; off <= 2; off <<= 1) {
            ps0 += __shfl_xor_sync(0xffffffffu, ps0, off);
            ps1 += __shfl_xor_sync(0xffffffffu, ps1, off);
        }
        l_i[0] = l_i[0] * corr0 + ps0;
        l_i[1] = l_i[1] * corr1 + ps1;
        m_i[0] = mnew0;
        m_i[1] = mnew1;
#pragma unroll
        for (int g = 0; g < 8; g++) {
            o[g][0] *= corr0; o[g][1] *= corr0;
            o[g][2] *= corr1; o[g][3] *= corr1;
        }

#pragma unroll
        for (int tk = 0; tk < 4; tk++) {
            uint32_t vbh[4][4], vbl[4][4];
#pragma unroll
            for (int j = 0; j < 4; j++) {
                uint32_t ao = (uint32_t)((tk * 16 + lr) * FQ_ROWB + (j * 16 + lc * 8) * 2);
                ldsm_x4_t(vbh[j], stg + 2 * FTILE_B + ao);
                ldsm_x4_t(vbl[j], stg + 3 * FTILE_B + ao);
            }
#pragma unroll
            for (int j = 0; j < 4; j++) {
                mma_bf16(o[2 * j],     pa_hi[tk], &vbh[j][0]);
                mma_bf16(o[2 * j],     pa_hi[tk], &vbl[j][0]);
                mma_bf16(o[2 * j],     pa_lo[tk], &vbh[j][0]);
                mma_bf16(o[2 * j + 1], pa_hi[tk], &vbh[j][2]);
                mma_bf16(o[2 * j + 1], pa_hi[tk], &vbl[j][2]);
                mma_bf16(o[2 * j + 1], pa_lo[tk], &vbh[j][2]);
            }
        }
        __syncthreads();
    }
#undef LOAD_KV

    const float inv0 = 1.0f / l_i[0];
    const float inv1 = 1.0f / l_i[1];
    const int row0 = qt * 64 + w * 16 + gq;
    const size_t base0 = (size_t)(b * SS + row0) * DD + h * HDIM;
    const size_t base1 = base0 + (size_t)8 * DD;
#pragma unroll
    for (int g = 0; g < 8; g++) {
        int col = g * 8 + tq * 2;
        float v0 = o[g][0] * inv0, v1 = o[g][1] * inv0;
        float v2 = o[g][2] * inv1, v3 = o[g][3] * inv1;
        __nv_bfloat16 h0, h1, h2, h3, l0, l1, l2, l3;
        split1(v0, h0, l0); split1(v1, h1, l1);
        split1(v2, h2, l2); split1(v3, h3, l3);
        __nv_bfloat162 ph0; ph0.x = h0; ph0.y = h1;
        __nv_bfloat162 pl0; pl0.x = l0; pl0.y = l1;
        __nv_bfloat162 ph1; ph1.x = h2; ph1.y = h3;
        __nv_bfloat162 pl1; pl1.x = l2; pl1.y = l3;
        *(__nv_bfloat162*)(g_mhi + base0 + col) = ph0;
        *(__nv_bfloat162*)(g_mlo + base0 + col) = pl0;
        *(__nv_bfloat162*)(g_mhi + base1 + col) = ph1;
        *(__nv_bfloat162*)(g_mlo + base1 + col) = pl1;
    }
}

// ---------------------------------------------------------------------------
extern "C" void kernel_launch(void* const* d_in, const int* in_sizes, int n_in,
                              void* d_out, int out_size) {
    const float* x    = (const float*)d_in[0];   // [B,S,D]
    const float* wqkv = (const float*)d_in[1];   // [D,3D]
    const float* wout = (const float*)d_in[2];   // [D,D]
    float*       out  = (float*)d_out;           // [B,S,D]

    __nv_bfloat16 *xhi, *xlo, *mhi, *mlo, *w1hi, *w1lo, *w2hi, *w2lo, *qhi, *qlo;
    cudaGetSymbolAddress((void**)&xhi, g_xhi);   cudaGetSymbolAddress((void**)&xlo, g_xlo);
    cudaGetSymbolAddress((void**)&mhi, g_mhi);   cudaGetSymbolAddress((void**)&mlo, g_mlo);
    cudaGetSymbolAddress((void**)&w1hi, g_w1hi); cudaGetSymbolAddress((void**)&w1lo, g_w1lo);
    cudaGetSymbolAddress((void**)&w2hi, g_w2hi); cudaGetSymbolAddress((void**)&w2lo, g_w2lo);
    cudaGetSymbolAddress((void**)&qhi, g_qkvhi); cudaGetSymbolAddress((void**)&qlo, g_qkvlo);

    cudaFuncSetAttribute(gemm_mma, cudaFuncAttributeMaxDynamicSharedMemorySize, GEMM_SMEM);
    cudaFuncSetAttribute(flash_mma, cudaFuncAttributeMaxDynamicSharedMemorySize, FL_SMEM);

    // 1) split inputs to bf16 hi/lo
    {
        int n4 = MTOT * DD / 4;
        convert_split<<<(n4 + 255) / 256, 256>>>(x, xhi, xlo, n4);
        int w1 = DD * QKVN / 4;
        convert_split<<<(w1 + 255) / 256, 256>>>(wqkv, w1hi, w1lo, w1);
        int w2 = DD * DD / 4;
        convert_split<<<(w2 + 255) / 256, 256>>>(wout, w2hi, w2lo, w2);
    }
    // 2) QKV GEMM -> bf16 hi/lo split output (consumed by flash)
    gemm_mma<<<dim3(QKVN / 128, MTOT / 128), 256, GEMM_SMEM>>>(
        xhi, xlo, w1hi, w1lo, nullptr, qhi, qlo, MTOT, QKVN, DD);
    // 3) flash attention on tensor cores -> merged bf16 hi/lo
    flash_mma<<<dim3(SS / 64, HH, BB), 128, FL_SMEM>>>();
    // 4) output GEMM -> fp32 out
    gemm_mma<<<dim3(DD / 128, MTOT / 128), 256, GEMM_SMEM>>>(
        mhi, mlo, w2hi, w2lo, out, nullptr, nullptr, MTOT, DD, DD);
}